// round 12
// baseline (speedup 1.0000x reference)
#include <cuda_runtime.h>

// IMU preintegration (RmiModel). Associative segment composition:
//   segment = (Q, p, r, tau);
//   compose: Q=Q1Q2, p=p1+Q1 p2, r=r1+tau2 p1+Q1 r2, tau=tau1+tau2.
// TWO BATCHES PER WARP, packed in f32x2 end-to-end: batch b0 = .lo,
// batch b1 = .hi. Each lane integrates 8 sequential packed steps (both
// batches at once), then a 5-stage shfl_down tree of PACKED composes
// reduces 32 lane segments — serving two batches per instruction.
// 4 warps cover 1024 steps of the batch pair; warp totals composed via smem.

typedef unsigned long long u64;

__device__ __forceinline__ u64 pk2(float lo, float hi) {
    u64 r;
    asm("mov.b64 %0, {%1, %2};" : "=l"(r)
        : "r"(__float_as_uint(lo)), "r"(__float_as_uint(hi)));
    return r;
}
__device__ __forceinline__ void up2(u64 v, float& lo, float& hi) {
    unsigned int a, b;
    asm("mov.b64 {%0, %1}, %2;" : "=r"(a), "=r"(b) : "l"(v));
    lo = __uint_as_float(a); hi = __uint_as_float(b);
}
__device__ __forceinline__ u64 dup2(float c) { return pk2(c, c); }
__device__ __forceinline__ u64 f2fma(u64 a, u64 b, u64 c) {
    u64 d; asm("fma.rn.f32x2 %0, %1, %2, %3;" : "=l"(d) : "l"(a), "l"(b), "l"(c)); return d;
}
__device__ __forceinline__ u64 f2mul(u64 a, u64 b) {
    u64 d; asm("mul.rn.f32x2 %0, %1, %2;" : "=l"(d) : "l"(a), "l"(b)); return d;
}
__device__ __forceinline__ u64 f2add(u64 a, u64 b) {
    u64 d; asm("add.rn.f32x2 %0, %1, %2;" : "=l"(d) : "l"(a), "l"(b)); return d;
}
__device__ __forceinline__ u64 f2neg(u64 a) { return a ^ 0x8000000080000000ULL; }

// Packed so3 exponential: R = I + A*K + Bc*(phi phi^T - t2 I), both halves.
__device__ __forceinline__ void pso3_R(u64 px, u64 py, u64 pz, u64 R[9]) {
    u64 px2 = f2mul(px, px), py2 = f2mul(py, py), pz2 = f2mul(pz, pz);
    u64 syz = f2add(py2, pz2), sxz = f2add(px2, pz2), sxy = f2add(px2, py2);
    u64 t2  = f2add(px2, syz);
    const u64 ONE = dup2(1.0f);
    u64 A  = f2fma(t2, dup2(1.0f/120.0f), dup2(-1.0f/6.0f));
    A      = f2fma(t2, A, ONE);
    u64 Bc = f2fma(t2, dup2(1.0f/720.0f), dup2(-1.0f/24.0f));
    Bc     = f2fma(t2, Bc, dup2(0.5f));

    // Cold exact fallback for large angles (never taken on this data).
    float t2lo, t2hi; up2(t2, t2lo, t2hi);
    if (__builtin_expect(fmaxf(t2lo, t2hi) > 0.25f, 0)) {
        float Alo, Ahi, Blo, Bhi;
        up2(A, Alo, Ahi); up2(Bc, Blo, Bhi);
        if (t2lo > 0.25f) {
            float th = __fsqrt_rn(t2lo); float s, c; __sincosf(th, &s, &c);
            Alo = s / th; Blo = (1.0f - c) / t2lo;
        }
        if (t2hi > 0.25f) {
            float th = __fsqrt_rn(t2hi); float s, c; __sincosf(th, &s, &c);
            Ahi = s / th; Bhi = (1.0f - c) / t2hi;
        }
        A = pk2(Alo, Ahi); Bc = pk2(Blo, Bhi);
    }

    u64 nBc = f2neg(Bc);
    u64 An  = f2neg(A);
    R[0] = f2fma(nBc, syz, ONE);
    R[4] = f2fma(nBc, sxz, ONE);
    R[8] = f2fma(nBc, sxy, ONE);
    u64 Bxy = f2mul(Bc, f2mul(px, py));
    u64 Bxz = f2mul(Bc, f2mul(px, pz));
    u64 Byz = f2mul(Bc, f2mul(py, pz));
    R[3] = f2fma(A,  pz, Bxy);
    R[1] = f2fma(An, pz, Bxy);
    R[2] = f2fma(A,  py, Bxz);
    R[6] = f2fma(An, py, Bxz);
    R[7] = f2fma(A,  px, Byz);
    R[5] = f2fma(An, px, Byz);
}

// First step from identity (packed both batches).
__device__ __forceinline__ void pstep0(u64 Q[9], u64 p[3], u64 r[3], u64& tau,
                                       u64 dt, u64 aX, u64 aY, u64 aZ,
                                       u64 wX, u64 wY, u64 wZ) {
    u64 hdt2 = f2mul(dup2(0.5f), f2mul(dt, dt));
    r[0] = f2mul(aX, hdt2); r[1] = f2mul(aY, hdt2); r[2] = f2mul(aZ, hdt2);
    p[0] = f2mul(aX, dt);   p[1] = f2mul(aY, dt);   p[2] = f2mul(aZ, dt);
    tau  = dt;
    pso3_R(f2mul(wX, dt), f2mul(wY, dt), f2mul(wZ, dt), Q);
}

// General packed step.
__device__ __forceinline__ void pstep(u64 Q[9], u64 p[3], u64 r[3], u64& tau,
                                      u64 dt, u64 aX, u64 aY, u64 aZ,
                                      u64 wX, u64 wY, u64 wZ) {
    u64 ca0 = f2fma(Q[0], aX, f2fma(Q[1], aY, f2mul(Q[2], aZ)));
    u64 ca1 = f2fma(Q[3], aX, f2fma(Q[4], aY, f2mul(Q[5], aZ)));
    u64 ca2 = f2fma(Q[6], aX, f2fma(Q[7], aY, f2mul(Q[8], aZ)));
    u64 hdt2 = f2mul(dup2(0.5f), f2mul(dt, dt));
    r[0] = f2fma(p[0], dt, f2fma(ca0, hdt2, r[0]));
    r[1] = f2fma(p[1], dt, f2fma(ca1, hdt2, r[1]));
    r[2] = f2fma(p[2], dt, f2fma(ca2, hdt2, r[2]));
    p[0] = f2fma(ca0, dt, p[0]);
    p[1] = f2fma(ca1, dt, p[1]);
    p[2] = f2fma(ca2, dt, p[2]);
    tau  = f2add(tau, dt);

    u64 R[9];
    pso3_R(f2mul(wX, dt), f2mul(wY, dt), f2mul(wZ, dt), R);

    u64 n0 = f2fma(Q[0], R[0], f2fma(Q[1], R[3], f2mul(Q[2], R[6])));
    u64 n1 = f2fma(Q[0], R[1], f2fma(Q[1], R[4], f2mul(Q[2], R[7])));
    u64 n2 = f2fma(Q[0], R[2], f2fma(Q[1], R[5], f2mul(Q[2], R[8])));
    u64 n3 = f2fma(Q[3], R[0], f2fma(Q[4], R[3], f2mul(Q[5], R[6])));
    u64 n4 = f2fma(Q[3], R[1], f2fma(Q[4], R[4], f2mul(Q[5], R[7])));
    u64 n5 = f2fma(Q[3], R[2], f2fma(Q[4], R[5], f2mul(Q[5], R[8])));
    u64 n6 = f2fma(Q[6], R[0], f2fma(Q[7], R[3], f2mul(Q[8], R[6])));
    u64 n7 = f2fma(Q[6], R[1], f2fma(Q[7], R[4], f2mul(Q[8], R[7])));
    u64 n8 = f2fma(Q[6], R[2], f2fma(Q[7], R[5], f2mul(Q[8], R[8])));
    Q[0]=n0; Q[1]=n1; Q[2]=n2;
    Q[3]=n3; Q[4]=n4; Q[5]=n5;
    Q[6]=n6; Q[7]=n7; Q[8]=n8;
}

// Packed compose: T1 <- T1 ∘ T2 (both batches at once).
__device__ __forceinline__ void pcompose(u64 Q1[9], u64 p1[3], u64 r1[3], u64& tau1,
                                         const u64 Q2[9], const u64 p2[3],
                                         const u64 r2[3], u64 tau2) {
    u64 nQ[9];
    #pragma unroll
    for (int i = 0; i < 3; i++) {
        #pragma unroll
        for (int j = 0; j < 3; j++)
            nQ[3*i+j] = f2fma(Q1[3*i+0], Q2[0+j],
                        f2fma(Q1[3*i+1], Q2[3+j],
                        f2mul(Q1[3*i+2], Q2[6+j])));
    }
    u64 np[3], nr[3];
    #pragma unroll
    for (int i = 0; i < 3; i++) {
        u64 Qp = f2fma(Q1[3*i+0], p2[0], f2fma(Q1[3*i+1], p2[1], f2mul(Q1[3*i+2], p2[2])));
        u64 Qr = f2fma(Q1[3*i+0], r2[0], f2fma(Q1[3*i+1], r2[1], f2mul(Q1[3*i+2], r2[2])));
        np[i] = f2add(p1[i], Qp);
        nr[i] = f2fma(tau2, p1[i], f2add(r1[i], Qr));
    }
    #pragma unroll
    for (int i = 0; i < 9; i++) Q1[i] = nQ[i];
    #pragma unroll
    for (int i = 0; i < 3; i++) { p1[i] = np[i]; r1[i] = nr[i]; }
    tau1 = f2add(tau1, tau2);
}

// Tail-guarded float2 channel load at element offset off.
__device__ __forceinline__ float2 loadc2(const float* __restrict__ xb, int off, int lim) {
    if (off + 1 < lim) {
        return *reinterpret_cast<const float2*>(xb + off);
    } else {
        float t0 = (off + 0 < lim) ? xb[off + 0] : 0.f;
        float t1 = (off + 1 < lim) ? xb[off + 1] : 0.f;
        return make_float2(t0, t1);
    }
}

// One 2-step packed phase: loads steps {kk, kk+1} of both batches (float2
// per channel), runs 2 packed steps. FIRST==true uses pstep0 for step kk.
template <bool FIRST>
__device__ __forceinline__ void phase2(const float* __restrict__ xb0,
                                       const float* __restrict__ xb1,
                                       int kk, int T, u64 DT0, u64 DT1,
                                       u64 Q[9], u64 p[3], u64 r[3], u64& tau) {
    float2 wx0 = loadc2(xb0, 1*T + kk, 2*T), wx1 = loadc2(xb1, 1*T + kk, 2*T);
    float2 wy0 = loadc2(xb0, 2*T + kk, 3*T), wy1 = loadc2(xb1, 2*T + kk, 3*T);
    float2 wz0 = loadc2(xb0, 3*T + kk, 4*T), wz1 = loadc2(xb1, 3*T + kk, 4*T);
    float2 ax0 = loadc2(xb0, 4*T + kk, 5*T), ax1 = loadc2(xb1, 4*T + kk, 5*T);
    float2 ay0 = loadc2(xb0, 5*T + kk, 6*T), ay1 = loadc2(xb1, 5*T + kk, 6*T);
    float2 az0 = loadc2(xb0, 6*T + kk, 7*T), az1 = loadc2(xb1, 6*T + kk, 7*T);

    if (FIRST) {
        pstep0(Q, p, r, tau, DT0,
               pk2(ax0.x, ax1.x), pk2(ay0.x, ay1.x), pk2(az0.x, az1.x),
               pk2(wx0.x, wx1.x), pk2(wy0.x, wy1.x), pk2(wz0.x, wz1.x));
    } else {
        pstep(Q, p, r, tau, DT0,
              pk2(ax0.x, ax1.x), pk2(ay0.x, ay1.x), pk2(az0.x, az1.x),
              pk2(wx0.x, wx1.x), pk2(wy0.x, wy1.x), pk2(wz0.x, wz1.x));
    }
    pstep(Q, p, r, tau, DT1,
          pk2(ax0.y, ax1.y), pk2(ay0.y, ay1.y), pk2(az0.y, az1.y),
          pk2(wx0.y, wx1.y), pk2(wy0.y, wy1.y), pk2(wz0.y, wz1.y));
}

// One 256-step round for this warp over the batch pair. Packed result
// (valid on lane 0) in (Q,p,r,tau).
__device__ __forceinline__ void warp_round(const float* __restrict__ xb0,
                                           const float* __restrict__ xb1,
                                           int k, int T, int nsteps, int lane,
                                           u64 Q[9], u64 p[3], u64 r[3], u64& tau) {
    // ---- time channels -> packed DT[8]; scalars die here ----
    u64 DT[8];
    {
        float tv0[8], tv1[8];
        if (k + 7 < T) {
            float4 u0 = *reinterpret_cast<const float4*>(xb0 + k);
            float4 v0 = *reinterpret_cast<const float4*>(xb0 + k + 4);
            tv0[0]=u0.x; tv0[1]=u0.y; tv0[2]=u0.z; tv0[3]=u0.w;
            tv0[4]=v0.x; tv0[5]=v0.y; tv0[6]=v0.z; tv0[7]=v0.w;
            float4 u1 = *reinterpret_cast<const float4*>(xb1 + k);
            float4 v1 = *reinterpret_cast<const float4*>(xb1 + k + 4);
            tv1[0]=u1.x; tv1[1]=u1.y; tv1[2]=u1.z; tv1[3]=u1.w;
            tv1[4]=v1.x; tv1[5]=v1.y; tv1[6]=v1.z; tv1[7]=v1.w;
        } else {
            #pragma unroll
            for (int j = 0; j < 8; j++) {
                tv0[j] = (k + j < T) ? xb0[k + j] : 0.f;
                tv1[j] = (k + j < T) ? xb1[k + j] : 0.f;
            }
        }
        float tn0 = __shfl_down_sync(0xffffffffu, tv0[0], 1);
        float tn1 = __shfl_down_sync(0xffffffffu, tv1[0], 1);
        if (lane == 31) {
            int kn = k + 8;
            tn0 = (kn < T) ? xb0[kn] : 0.f;
            tn1 = (kn < T) ? xb1[kn] : 0.f;
        }
        #pragma unroll
        for (int j = 0; j < 8; j++) {
            float d0 = ((j < 7) ? tv0[j + 1] : tn0) - tv0[j];
            float d1 = ((j < 7) ? tv1[j + 1] : tn1) - tv1[j];
            DT[j] = (k + j < nsteps) ? pk2(d0, d1) : 0ULL;   // identity step
        }
    }

    // ---- 8 sequential packed steps in four 2-step phases ----
    phase2<true >(xb0, xb1, k    , T, DT[0], DT[1], Q, p, r, tau);
    phase2<false>(xb0, xb1, k + 2, T, DT[2], DT[3], Q, p, r, tau);
    phase2<false>(xb0, xb1, k + 4, T, DT[4], DT[5], Q, p, r, tau);
    phase2<false>(xb0, xb1, k + 6, T, DT[6], DT[7], Q, p, r, tau);

    // ---- warp tree reduce, PACKED composes (both batches per instr) ----
    #pragma unroll
    for (int off = 1; off < 32; off <<= 1) {
        u64 Q2[9], p2[3], r2[3], tau2;
        #pragma unroll
        for (int i = 0; i < 9; i++) Q2[i] = __shfl_down_sync(0xffffffffu, Q[i], off);
        #pragma unroll
        for (int i = 0; i < 3; i++) p2[i] = __shfl_down_sync(0xffffffffu, p[i], off);
        #pragma unroll
        for (int i = 0; i < 3; i++) r2[i] = __shfl_down_sync(0xffffffffu, r[i], off);
        tau2 = __shfl_down_sync(0xffffffffu, tau, off);
        pcompose(Q, p, r, tau, Q2, p2, r2, tau2);
    }
}

__global__ __launch_bounds__(128, 5)
void rmi_kernel(const float* __restrict__ x, float* __restrict__ out,
                int T, int chunk, int B)
{
    const int warp = threadIdx.x >> 5;
    const int lane = threadIdx.x & 31;
    const int nsteps = T - 1;

    const int b0 = 2 * blockIdx.x;
    const int b1 = (b0 + 1 < B) ? b0 + 1 : b0;
    const float* xb0 = x + (size_t)b0 * 7 * (size_t)T;
    const float* xb1 = x + (size_t)b1 * 7 * (size_t)T;

    const int rounds = chunk >> 8;   // 256 steps per round

    // Round 0 -> warp total directly
    u64 TQ[9], Tp[3], Tr[3], Ttau;
    warp_round(xb0, xb1, warp * chunk + lane * 8, T, nsteps, lane, TQ, Tp, Tr, Ttau);

    for (int rr = 1; rr < rounds; rr++) {
        u64 Q[9], p[3], r[3], tau;
        warp_round(xb0, xb1, warp * chunk + rr * 256 + lane * 8, T, nsteps, lane,
                   Q, p, r, tau);
        pcompose(TQ, Tp, Tr, Ttau, Q, p, r, tau);
    }

    // ---- cross-warp combine via smem (packed) ----
    __shared__ u64 seg[4][16];
    if (lane == 0) {
        #pragma unroll
        for (int i = 0; i < 9; i++) seg[warp][i] = TQ[i];
        seg[warp][9]  = Tp[0]; seg[warp][10] = Tp[1]; seg[warp][11] = Tp[2];
        seg[warp][12] = Tr[0]; seg[warp][13] = Tr[1]; seg[warp][14] = Tr[2];
        seg[warp][15] = Ttau;
    }
    __syncthreads();

    if (warp == 0 && lane == 0) {
        u64 FQ[9], Fp[3], Fr[3], Ftau;
        #pragma unroll
        for (int i = 0; i < 9; i++) FQ[i] = seg[0][i];
        Fp[0]=seg[0][9];  Fp[1]=seg[0][10]; Fp[2]=seg[0][11];
        Fr[0]=seg[0][12]; Fr[1]=seg[0][13]; Fr[2]=seg[0][14];
        Ftau = seg[0][15];
        #pragma unroll
        for (int wsg = 1; wsg < 4; wsg++) {
            u64 Q2[9], p2[3], r2[3], tau2;
            #pragma unroll
            for (int i = 0; i < 9; i++) Q2[i] = seg[wsg][i];
            p2[0]=seg[wsg][9];  p2[1]=seg[wsg][10]; p2[2]=seg[wsg][11];
            r2[0]=seg[wsg][12]; r2[1]=seg[wsg][13]; r2[2]=seg[wsg][14];
            tau2 = seg[wsg][15];
            pcompose(FQ, Fp, Fr, Ftau, Q2, p2, r2, tau2);
        }
        float* o0 = out + (size_t)b0 * 15;
        float* o1 = out + (size_t)b1 * 15;
        #pragma unroll
        for (int i = 0; i < 9; i++) {
            float lo, hi; up2(FQ[i], lo, hi);
            o0[i] = lo; o1[i] = hi;
        }
        #pragma unroll
        for (int i = 0; i < 3; i++) {
            float lo, hi;
            up2(Fp[i], lo, hi); o0[9 + i]  = lo; o1[9 + i]  = hi;
            up2(Fr[i], lo, hi); o0[12 + i] = lo; o1[12 + i] = hi;
        }
    }
}

extern "C" void kernel_launch(void* const* d_in, const int* in_sizes, int n_in,
                              void* d_out, int out_size) {
    const float* x = (const float*)d_in[0];
    float* out = (float*)d_out;

    int B = out_size / 15;
    int T = in_sizes[0] / (7 * B);
    int nsteps = T - 1;

    // per-warp contiguous chunk, multiple of 256, 4 warps cover all steps
    int chunk = ((nsteps + 1023) / 1024) * 256;

    int blocks = (B + 1) / 2;     // one block per batch pair
    rmi_kernel<<<blocks, 128>>>(x, out, T, chunk, B);
}

// round 13
// speedup vs baseline: 1.1212x; 1.1212x over previous
#include <cuda_runtime.h>

// IMU preintegration (RmiModel). Associative segment composition:
//   segment = (Q, p, r, tau);
//   compose: Q=Q1Q2, p=p1+Q1 p2, r=r1+tau2 p1+Q1 r2, tau=tau1+tau2.
// TWO BATCHES PER WARP packed in f32x2 end-to-end (b0=.lo, b1=.hi):
// 8 sequential packed steps per lane (two float4-load phases of 4 steps),
// then a 5-stage shfl_down tree of PACKED composes — every tree/step
// instruction serves both batches. 4 warps cover 1024 steps of the pair;
// warp totals composed (packed) via smem. LDG count and L1 wavefronts per
// batch match the best scalar kernel (14 LDG.128/batch/lane-round).

typedef unsigned long long u64;

__device__ __forceinline__ u64 pk2(float lo, float hi) {
    u64 r;
    asm("mov.b64 %0, {%1, %2};" : "=l"(r)
        : "r"(__float_as_uint(lo)), "r"(__float_as_uint(hi)));
    return r;
}
__device__ __forceinline__ void up2(u64 v, float& lo, float& hi) {
    unsigned int a, b;
    asm("mov.b64 {%0, %1}, %2;" : "=r"(a), "=r"(b) : "l"(v));
    lo = __uint_as_float(a); hi = __uint_as_float(b);
}
__device__ __forceinline__ u64 dup2(float c) { return pk2(c, c); }
__device__ __forceinline__ u64 f2fma(u64 a, u64 b, u64 c) {
    u64 d; asm("fma.rn.f32x2 %0, %1, %2, %3;" : "=l"(d) : "l"(a), "l"(b), "l"(c)); return d;
}
__device__ __forceinline__ u64 f2mul(u64 a, u64 b) {
    u64 d; asm("mul.rn.f32x2 %0, %1, %2;" : "=l"(d) : "l"(a), "l"(b)); return d;
}
__device__ __forceinline__ u64 f2add(u64 a, u64 b) {
    u64 d; asm("add.rn.f32x2 %0, %1, %2;" : "=l"(d) : "l"(a), "l"(b)); return d;
}
__device__ __forceinline__ u64 f2neg(u64 a) { return a ^ 0x8000000080000000ULL; }

// Packed so3 exponential: R = I + A*K + Bc*(phi phi^T - t2 I), both halves.
// Depends only on inputs (w*dt) — off the Q critical path.
__device__ __forceinline__ void pso3_R(u64 px, u64 py, u64 pz, u64 R[9]) {
    u64 px2 = f2mul(px, px), py2 = f2mul(py, py), pz2 = f2mul(pz, pz);
    u64 syz = f2add(py2, pz2), sxz = f2add(px2, pz2), sxy = f2add(px2, py2);
    u64 t2  = f2add(px2, syz);
    const u64 ONE = dup2(1.0f);
    u64 A  = f2fma(t2, dup2(1.0f/120.0f), dup2(-1.0f/6.0f));
    A      = f2fma(t2, A, ONE);
    u64 Bc = f2fma(t2, dup2(1.0f/720.0f), dup2(-1.0f/24.0f));
    Bc     = f2fma(t2, Bc, dup2(0.5f));

    // Cold exact fallback for large angles (never taken on this data).
    float t2lo, t2hi; up2(t2, t2lo, t2hi);
    if (__builtin_expect(fmaxf(t2lo, t2hi) > 0.25f, 0)) {
        float Alo, Ahi, Blo, Bhi;
        up2(A, Alo, Ahi); up2(Bc, Blo, Bhi);
        if (t2lo > 0.25f) {
            float th = __fsqrt_rn(t2lo); float s, c; __sincosf(th, &s, &c);
            Alo = s / th; Blo = (1.0f - c) / t2lo;
        }
        if (t2hi > 0.25f) {
            float th = __fsqrt_rn(t2hi); float s, c; __sincosf(th, &s, &c);
            Ahi = s / th; Bhi = (1.0f - c) / t2hi;
        }
        A = pk2(Alo, Ahi); Bc = pk2(Blo, Bhi);
    }

    u64 nBc = f2neg(Bc);
    u64 An  = f2neg(A);
    R[0] = f2fma(nBc, syz, ONE);
    R[4] = f2fma(nBc, sxz, ONE);
    R[8] = f2fma(nBc, sxy, ONE);
    u64 Bxy = f2mul(Bc, f2mul(px, py));
    u64 Bxz = f2mul(Bc, f2mul(px, pz));
    u64 Byz = f2mul(Bc, f2mul(py, pz));
    R[3] = f2fma(A,  pz, Bxy);
    R[1] = f2fma(An, pz, Bxy);
    R[2] = f2fma(A,  py, Bxz);
    R[6] = f2fma(An, py, Bxz);
    R[7] = f2fma(A,  px, Byz);
    R[5] = f2fma(An, px, Byz);
}

// First step from identity (packed both batches).
__device__ __forceinline__ void pstep0(u64 Q[9], u64 p[3], u64 r[3], u64& tau,
                                       u64 dt, u64 aX, u64 aY, u64 aZ,
                                       u64 wX, u64 wY, u64 wZ) {
    u64 hdt2 = f2mul(dup2(0.5f), f2mul(dt, dt));
    r[0] = f2mul(aX, hdt2); r[1] = f2mul(aY, hdt2); r[2] = f2mul(aZ, hdt2);
    p[0] = f2mul(aX, dt);   p[1] = f2mul(aY, dt);   p[2] = f2mul(aZ, dt);
    tau  = dt;
    pso3_R(f2mul(wX, dt), f2mul(wY, dt), f2mul(wZ, dt), Q);
}

// General packed step.
__device__ __forceinline__ void pstep(u64 Q[9], u64 p[3], u64 r[3], u64& tau,
                                      u64 dt, u64 aX, u64 aY, u64 aZ,
                                      u64 wX, u64 wY, u64 wZ) {
    u64 ca0 = f2fma(Q[0], aX, f2fma(Q[1], aY, f2mul(Q[2], aZ)));
    u64 ca1 = f2fma(Q[3], aX, f2fma(Q[4], aY, f2mul(Q[5], aZ)));
    u64 ca2 = f2fma(Q[6], aX, f2fma(Q[7], aY, f2mul(Q[8], aZ)));
    u64 hdt2 = f2mul(dup2(0.5f), f2mul(dt, dt));
    r[0] = f2fma(p[0], dt, f2fma(ca0, hdt2, r[0]));
    r[1] = f2fma(p[1], dt, f2fma(ca1, hdt2, r[1]));
    r[2] = f2fma(p[2], dt, f2fma(ca2, hdt2, r[2]));
    p[0] = f2fma(ca0, dt, p[0]);
    p[1] = f2fma(ca1, dt, p[1]);
    p[2] = f2fma(ca2, dt, p[2]);
    tau  = f2add(tau, dt);

    u64 R[9];
    pso3_R(f2mul(wX, dt), f2mul(wY, dt), f2mul(wZ, dt), R);

    u64 n0 = f2fma(Q[0], R[0], f2fma(Q[1], R[3], f2mul(Q[2], R[6])));
    u64 n1 = f2fma(Q[0], R[1], f2fma(Q[1], R[4], f2mul(Q[2], R[7])));
    u64 n2 = f2fma(Q[0], R[2], f2fma(Q[1], R[5], f2mul(Q[2], R[8])));
    u64 n3 = f2fma(Q[3], R[0], f2fma(Q[4], R[3], f2mul(Q[5], R[6])));
    u64 n4 = f2fma(Q[3], R[1], f2fma(Q[4], R[4], f2mul(Q[5], R[7])));
    u64 n5 = f2fma(Q[3], R[2], f2fma(Q[4], R[5], f2mul(Q[5], R[8])));
    u64 n6 = f2fma(Q[6], R[0], f2fma(Q[7], R[3], f2mul(Q[8], R[6])));
    u64 n7 = f2fma(Q[6], R[1], f2fma(Q[7], R[4], f2mul(Q[8], R[7])));
    u64 n8 = f2fma(Q[6], R[2], f2fma(Q[7], R[5], f2mul(Q[8], R[8])));
    Q[0]=n0; Q[1]=n1; Q[2]=n2;
    Q[3]=n3; Q[4]=n4; Q[5]=n5;
    Q[6]=n6; Q[7]=n7; Q[8]=n8;
}

// Packed compose: T1 <- T1 ∘ T2 (both batches at once).
__device__ __forceinline__ void pcompose(u64 Q1[9], u64 p1[3], u64 r1[3], u64& tau1,
                                         const u64 Q2[9], const u64 p2[3],
                                         const u64 r2[3], u64 tau2) {
    u64 nQ[9];
    #pragma unroll
    for (int i = 0; i < 3; i++) {
        #pragma unroll
        for (int j = 0; j < 3; j++)
            nQ[3*i+j] = f2fma(Q1[3*i+0], Q2[0+j],
                        f2fma(Q1[3*i+1], Q2[3+j],
                        f2mul(Q1[3*i+2], Q2[6+j])));
    }
    u64 np[3], nr[3];
    #pragma unroll
    for (int i = 0; i < 3; i++) {
        u64 Qp = f2fma(Q1[3*i+0], p2[0], f2fma(Q1[3*i+1], p2[1], f2mul(Q1[3*i+2], p2[2])));
        u64 Qr = f2fma(Q1[3*i+0], r2[0], f2fma(Q1[3*i+1], r2[1], f2mul(Q1[3*i+2], r2[2])));
        np[i] = f2add(p1[i], Qp);
        nr[i] = f2fma(tau2, p1[i], f2add(r1[i], Qr));
    }
    #pragma unroll
    for (int i = 0; i < 9; i++) Q1[i] = nQ[i];
    #pragma unroll
    for (int i = 0; i < 3; i++) { p1[i] = np[i]; r1[i] = nr[i]; }
    tau1 = f2add(tau1, tau2);
}

// Tail-guarded float4 channel load at element offset off.
__device__ __forceinline__ float4 loadc(const float* __restrict__ xb, int off, int lim) {
    if (off + 3 < lim) {
        return *reinterpret_cast<const float4*>(xb + off);
    } else {
        float t0 = (off + 0 < lim) ? xb[off + 0] : 0.f;
        float t1 = (off + 1 < lim) ? xb[off + 1] : 0.f;
        float t2 = (off + 2 < lim) ? xb[off + 2] : 0.f;
        float t3 = (off + 3 < lim) ? xb[off + 3] : 0.f;
        return make_float4(t0, t1, t2, t3);
    }
}

// One 4-step packed phase: float4 per channel per batch (12 LDG.128),
// 4 packed steps. FIRST==true uses pstep0 for the first step.
template <bool FIRST>
__device__ __forceinline__ void phase4(const float* __restrict__ xb0,
                                       const float* __restrict__ xb1,
                                       int kk, int T, const u64* DT,
                                       u64 Q[9], u64 p[3], u64 r[3], u64& tau) {
    float4 wx0 = loadc(xb0, 1*T + kk, 2*T), wx1 = loadc(xb1, 1*T + kk, 2*T);
    float4 wy0 = loadc(xb0, 2*T + kk, 3*T), wy1 = loadc(xb1, 2*T + kk, 3*T);
    float4 wz0 = loadc(xb0, 3*T + kk, 4*T), wz1 = loadc(xb1, 3*T + kk, 4*T);
    float4 ax0 = loadc(xb0, 4*T + kk, 5*T), ax1 = loadc(xb1, 4*T + kk, 5*T);
    float4 ay0 = loadc(xb0, 5*T + kk, 6*T), ay1 = loadc(xb1, 5*T + kk, 6*T);
    float4 az0 = loadc(xb0, 6*T + kk, 7*T), az1 = loadc(xb1, 6*T + kk, 7*T);

    if (FIRST) {
        pstep0(Q, p, r, tau, DT[0],
               pk2(ax0.x, ax1.x), pk2(ay0.x, ay1.x), pk2(az0.x, az1.x),
               pk2(wx0.x, wx1.x), pk2(wy0.x, wy1.x), pk2(wz0.x, wz1.x));
    } else {
        pstep(Q, p, r, tau, DT[0],
              pk2(ax0.x, ax1.x), pk2(ay0.x, ay1.x), pk2(az0.x, az1.x),
              pk2(wx0.x, wx1.x), pk2(wy0.x, wy1.x), pk2(wz0.x, wz1.x));
    }
    pstep(Q, p, r, tau, DT[1],
          pk2(ax0.y, ax1.y), pk2(ay0.y, ay1.y), pk2(az0.y, az1.y),
          pk2(wx0.y, wx1.y), pk2(wy0.y, wy1.y), pk2(wz0.y, wz1.y));
    pstep(Q, p, r, tau, DT[2],
          pk2(ax0.z, ax1.z), pk2(ay0.z, ay1.z), pk2(az0.z, az1.z),
          pk2(wx0.z, wx1.z), pk2(wy0.z, wy1.z), pk2(wz0.z, wz1.z));
    pstep(Q, p, r, tau, DT[3],
          pk2(ax0.w, ax1.w), pk2(ay0.w, ay1.w), pk2(az0.w, az1.w),
          pk2(wx0.w, wx1.w), pk2(wy0.w, wy1.w), pk2(wz0.w, wz1.w));
}

// One 256-step round for this warp over the batch pair. Packed result
// (valid on lane 0) in (Q,p,r,tau).
__device__ __forceinline__ void warp_round(const float* __restrict__ xb0,
                                           const float* __restrict__ xb1,
                                           int k, int T, int nsteps, int lane,
                                           u64 Q[9], u64 p[3], u64 r[3], u64& tau) {
    // ---- time channels -> packed DT[8]; scalars die here ----
    u64 DT[8];
    {
        float tv0[8], tv1[8];
        if (k + 7 < T) {
            float4 u0 = *reinterpret_cast<const float4*>(xb0 + k);
            float4 v0 = *reinterpret_cast<const float4*>(xb0 + k + 4);
            tv0[0]=u0.x; tv0[1]=u0.y; tv0[2]=u0.z; tv0[3]=u0.w;
            tv0[4]=v0.x; tv0[5]=v0.y; tv0[6]=v0.z; tv0[7]=v0.w;
            float4 u1 = *reinterpret_cast<const float4*>(xb1 + k);
            float4 v1 = *reinterpret_cast<const float4*>(xb1 + k + 4);
            tv1[0]=u1.x; tv1[1]=u1.y; tv1[2]=u1.z; tv1[3]=u1.w;
            tv1[4]=v1.x; tv1[5]=v1.y; tv1[6]=v1.z; tv1[7]=v1.w;
        } else {
            #pragma unroll
            for (int j = 0; j < 8; j++) {
                tv0[j] = (k + j < T) ? xb0[k + j] : 0.f;
                tv1[j] = (k + j < T) ? xb1[k + j] : 0.f;
            }
        }
        float tn0 = __shfl_down_sync(0xffffffffu, tv0[0], 1);
        float tn1 = __shfl_down_sync(0xffffffffu, tv1[0], 1);
        if (lane == 31) {
            int kn = k + 8;
            tn0 = (kn < T) ? xb0[kn] : 0.f;
            tn1 = (kn < T) ? xb1[kn] : 0.f;
        }
        #pragma unroll
        for (int j = 0; j < 8; j++) {
            float d0 = ((j < 7) ? tv0[j + 1] : tn0) - tv0[j];
            float d1 = ((j < 7) ? tv1[j + 1] : tn1) - tv1[j];
            DT[j] = (k + j < nsteps) ? pk2(d0, d1) : 0ULL;   // identity step
        }
    }

    // ---- 8 sequential packed steps in two 4-step phases (float4 loads) ----
    phase4<true >(xb0, xb1, k    , T, DT    , Q, p, r, tau);
    phase4<false>(xb0, xb1, k + 4, T, DT + 4, Q, p, r, tau);

    // ---- warp tree reduce, PACKED composes (both batches per instr) ----
    #pragma unroll
    for (int off = 1; off < 32; off <<= 1) {
        u64 Q2[9], p2[3], r2[3], tau2;
        #pragma unroll
        for (int i = 0; i < 9; i++) Q2[i] = __shfl_down_sync(0xffffffffu, Q[i], off);
        #pragma unroll
        for (int i = 0; i < 3; i++) p2[i] = __shfl_down_sync(0xffffffffu, p[i], off);
        #pragma unroll
        for (int i = 0; i < 3; i++) r2[i] = __shfl_down_sync(0xffffffffu, r[i], off);
        tau2 = __shfl_down_sync(0xffffffffu, tau, off);
        pcompose(Q, p, r, tau, Q2, p2, r2, tau2);
    }
}

__global__ __launch_bounds__(128, 4)
void rmi_kernel(const float* __restrict__ x, float* __restrict__ out,
                int T, int chunk, int B)
{
    const int warp = threadIdx.x >> 5;
    const int lane = threadIdx.x & 31;
    const int nsteps = T - 1;

    const int b0 = 2 * blockIdx.x;
    const int b1 = (b0 + 1 < B) ? b0 + 1 : b0;
    const float* xb0 = x + (size_t)b0 * 7 * (size_t)T;
    const float* xb1 = x + (size_t)b1 * 7 * (size_t)T;

    const int rounds = chunk >> 8;   // 256 steps per round

    // Round 0 -> warp total directly
    u64 TQ[9], Tp[3], Tr[3], Ttau;
    warp_round(xb0, xb1, warp * chunk + lane * 8, T, nsteps, lane, TQ, Tp, Tr, Ttau);

    for (int rr = 1; rr < rounds; rr++) {
        u64 Q[9], p[3], r[3], tau;
        warp_round(xb0, xb1, warp * chunk + rr * 256 + lane * 8, T, nsteps, lane,
                   Q, p, r, tau);
        pcompose(TQ, Tp, Tr, Ttau, Q, p, r, tau);
    }

    // ---- cross-warp combine via smem (packed) ----
    __shared__ u64 seg[4][16];
    if (lane == 0) {
        #pragma unroll
        for (int i = 0; i < 9; i++) seg[warp][i] = TQ[i];
        seg[warp][9]  = Tp[0]; seg[warp][10] = Tp[1]; seg[warp][11] = Tp[2];
        seg[warp][12] = Tr[0]; seg[warp][13] = Tr[1]; seg[warp][14] = Tr[2];
        seg[warp][15] = Ttau;
    }
    __syncthreads();

    if (warp == 0 && lane == 0) {
        u64 FQ[9], Fp[3], Fr[3], Ftau;
        #pragma unroll
        for (int i = 0; i < 9; i++) FQ[i] = seg[0][i];
        Fp[0]=seg[0][9];  Fp[1]=seg[0][10]; Fp[2]=seg[0][11];
        Fr[0]=seg[0][12]; Fr[1]=seg[0][13]; Fr[2]=seg[0][14];
        Ftau = seg[0][15];
        #pragma unroll
        for (int wsg = 1; wsg < 4; wsg++) {
            u64 Q2[9], p2[3], r2[3], tau2;
            #pragma unroll
            for (int i = 0; i < 9; i++) Q2[i] = seg[wsg][i];
            p2[0]=seg[wsg][9];  p2[1]=seg[wsg][10]; p2[2]=seg[wsg][11];
            r2[0]=seg[wsg][12]; r2[1]=seg[wsg][13]; r2[2]=seg[wsg][14];
            tau2 = seg[wsg][15];
            pcompose(FQ, Fp, Fr, Ftau, Q2, p2, r2, tau2);
        }
        float* o0 = out + (size_t)b0 * 15;
        float* o1 = out + (size_t)b1 * 15;
        #pragma unroll
        for (int i = 0; i < 9; i++) {
            float lo, hi; up2(FQ[i], lo, hi);
            o0[i] = lo; o1[i] = hi;
        }
        #pragma unroll
        for (int i = 0; i < 3; i++) {
            float lo, hi;
            up2(Fp[i], lo, hi); o0[9 + i]  = lo; o1[9 + i]  = hi;
            up2(Fr[i], lo, hi); o0[12 + i] = lo; o1[12 + i] = hi;
        }
    }
}

extern "C" void kernel_launch(void* const* d_in, const int* in_sizes, int n_in,
                              void* d_out, int out_size) {
    const float* x = (const float*)d_in[0];
    float* out = (float*)d_out;

    int B = out_size / 15;
    int T = in_sizes[0] / (7 * B);
    int nsteps = T - 1;

    // per-warp contiguous chunk, multiple of 256, 4 warps cover all steps
    int chunk = ((nsteps + 1023) / 1024) * 256;

    int blocks = (B + 1) / 2;     // one block per batch pair
    rmi_kernel<<<blocks, 128>>>(x, out, T, chunk, B);
}

// round 14
// speedup vs baseline: 1.2772x; 1.1391x over previous
#include <cuda_runtime.h>

// IMU preintegration (RmiModel). Associative segment composition:
//   segment = (Q, p, r, tau);
//   compose: Q=Q1Q2, p=p1+Q1 p2, r=r1+tau2 p1+Q1 r2, tau=tau1+tau2.
// 4 warps per batch (block = 128 thr = 1 batch). Each lane integrates 8
// contiguous steps as TWO chains of 4 steps PACKED into f32x2 (A=.lo, B=.hi),
// one scalar compose merges A∘B, then a 5-stage shfl_down tree composes the
// 32 lane segments (valid on lane 0). Warp totals composed via smem.
// Branch diet vs the 29.2us baseline: pso3 fallback checks are DEFERRED to
// one per round (accumulated packed t2, cold exact re-integration), and all
// load bounds checks are hoisted into one `fast` branch. 11 BSSY/BSYNC pairs
// per round -> 2.

typedef unsigned long long u64;

__device__ __forceinline__ u64 pk2(float lo, float hi) {
    u64 r;
    asm("mov.b64 %0, {%1, %2};" : "=l"(r)
        : "r"(__float_as_uint(lo)), "r"(__float_as_uint(hi)));
    return r;
}
__device__ __forceinline__ void up2(u64 v, float& lo, float& hi) {
    unsigned int a, b;
    asm("mov.b64 {%0, %1}, %2;" : "=r"(a), "=r"(b) : "l"(v));
    lo = __uint_as_float(a); hi = __uint_as_float(b);
}
__device__ __forceinline__ u64 dup2(float c) { return pk2(c, c); }
__device__ __forceinline__ u64 f2fma(u64 a, u64 b, u64 c) {
    u64 d; asm("fma.rn.f32x2 %0, %1, %2, %3;" : "=l"(d) : "l"(a), "l"(b), "l"(c)); return d;
}
__device__ __forceinline__ u64 f2mul(u64 a, u64 b) {
    u64 d; asm("mul.rn.f32x2 %0, %1, %2;" : "=l"(d) : "l"(a), "l"(b)); return d;
}
__device__ __forceinline__ u64 f2add(u64 a, u64 b) {
    u64 d; asm("add.rn.f32x2 %0, %1, %2;" : "=l"(d) : "l"(a), "l"(b)); return d;
}
__device__ __forceinline__ u64 f2neg(u64 a) { return a ^ 0x8000000080000000ULL; }

// Packed so3 exponential, PURE TAYLOR (validity check deferred to caller
// via acc += t2). R = I + A*K + Bc*(phi phi^T - t2 I), both halves.
__device__ __forceinline__ void pso3_R(u64 px, u64 py, u64 pz, u64 R[9], u64& acc) {
    u64 px2 = f2mul(px, px), py2 = f2mul(py, py), pz2 = f2mul(pz, pz);
    u64 syz = f2add(py2, pz2), sxz = f2add(px2, pz2), sxy = f2add(px2, py2);
    u64 t2  = f2add(px2, syz);
    acc = f2add(acc, t2);
    const u64 ONE = dup2(1.0f);
    u64 A  = f2fma(t2, dup2(1.0f/120.0f), dup2(-1.0f/6.0f));
    A      = f2fma(t2, A, ONE);
    u64 Bc = f2fma(t2, dup2(1.0f/720.0f), dup2(-1.0f/24.0f));
    Bc     = f2fma(t2, Bc, dup2(0.5f));

    u64 nBc = f2neg(Bc);
    u64 An  = f2neg(A);
    R[0] = f2fma(nBc, syz, ONE);
    R[4] = f2fma(nBc, sxz, ONE);
    R[8] = f2fma(nBc, sxy, ONE);
    u64 Bxy = f2mul(Bc, f2mul(px, py));
    u64 Bxz = f2mul(Bc, f2mul(px, pz));
    u64 Byz = f2mul(Bc, f2mul(py, pz));
    R[3] = f2fma(A,  pz, Bxy);
    R[1] = f2fma(An, pz, Bxy);
    R[2] = f2fma(A,  py, Bxz);
    R[6] = f2fma(An, py, Bxz);
    R[7] = f2fma(A,  px, Byz);
    R[5] = f2fma(An, px, Byz);
}

// First step from identity (packed both chains).
__device__ __forceinline__ void pstep0(u64 Q[9], u64 p[3], u64 r[3], u64& tau,
                                       u64 dt, u64 aX, u64 aY, u64 aZ,
                                       u64 wX, u64 wY, u64 wZ, u64& acc) {
    u64 hdt2 = f2mul(dup2(0.5f), f2mul(dt, dt));
    r[0] = f2mul(aX, hdt2); r[1] = f2mul(aY, hdt2); r[2] = f2mul(aZ, hdt2);
    p[0] = f2mul(aX, dt);   p[1] = f2mul(aY, dt);   p[2] = f2mul(aZ, dt);
    tau  = dt;
    pso3_R(f2mul(wX, dt), f2mul(wY, dt), f2mul(wZ, dt), Q, acc);
}

// General packed step.
__device__ __forceinline__ void pstep(u64 Q[9], u64 p[3], u64 r[3], u64& tau,
                                      u64 dt, u64 aX, u64 aY, u64 aZ,
                                      u64 wX, u64 wY, u64 wZ, u64& acc) {
    u64 ca0 = f2fma(Q[0], aX, f2fma(Q[1], aY, f2mul(Q[2], aZ)));
    u64 ca1 = f2fma(Q[3], aX, f2fma(Q[4], aY, f2mul(Q[5], aZ)));
    u64 ca2 = f2fma(Q[6], aX, f2fma(Q[7], aY, f2mul(Q[8], aZ)));
    u64 hdt2 = f2mul(dup2(0.5f), f2mul(dt, dt));
    r[0] = f2fma(p[0], dt, f2fma(ca0, hdt2, r[0]));
    r[1] = f2fma(p[1], dt, f2fma(ca1, hdt2, r[1]));
    r[2] = f2fma(p[2], dt, f2fma(ca2, hdt2, r[2]));
    p[0] = f2fma(ca0, dt, p[0]);
    p[1] = f2fma(ca1, dt, p[1]);
    p[2] = f2fma(ca2, dt, p[2]);
    tau  = f2add(tau, dt);

    u64 R[9];
    pso3_R(f2mul(wX, dt), f2mul(wY, dt), f2mul(wZ, dt), R, acc);

    u64 n0 = f2fma(Q[0], R[0], f2fma(Q[1], R[3], f2mul(Q[2], R[6])));
    u64 n1 = f2fma(Q[0], R[1], f2fma(Q[1], R[4], f2mul(Q[2], R[7])));
    u64 n2 = f2fma(Q[0], R[2], f2fma(Q[1], R[5], f2mul(Q[2], R[8])));
    u64 n3 = f2fma(Q[3], R[0], f2fma(Q[4], R[3], f2mul(Q[5], R[6])));
    u64 n4 = f2fma(Q[3], R[1], f2fma(Q[4], R[4], f2mul(Q[5], R[7])));
    u64 n5 = f2fma(Q[3], R[2], f2fma(Q[4], R[5], f2mul(Q[5], R[8])));
    u64 n6 = f2fma(Q[6], R[0], f2fma(Q[7], R[3], f2mul(Q[8], R[6])));
    u64 n7 = f2fma(Q[6], R[1], f2fma(Q[7], R[4], f2mul(Q[8], R[7])));
    u64 n8 = f2fma(Q[6], R[2], f2fma(Q[7], R[5], f2mul(Q[8], R[8])));
    Q[0]=n0; Q[1]=n1; Q[2]=n2;
    Q[3]=n3; Q[4]=n4; Q[5]=n5;
    Q[6]=n6; Q[7]=n7; Q[8]=n8;
}

// Scalar compose: T1 <- T1 ∘ T2
__device__ __forceinline__ void compose(float Q1[9], float p1[3], float r1[3], float& tau1,
                                        const float Q2[9], const float p2[3],
                                        const float r2[3], float tau2) {
    float nQ[9];
    #pragma unroll
    for (int i = 0; i < 3; i++) {
        #pragma unroll
        for (int j = 0; j < 3; j++)
            nQ[3*i+j] = Q1[3*i+0]*Q2[0+j] + Q1[3*i+1]*Q2[3+j] + Q1[3*i+2]*Q2[6+j];
    }
    float np[3], nr[3];
    #pragma unroll
    for (int i = 0; i < 3; i++) {
        float Qp = Q1[3*i+0]*p2[0] + Q1[3*i+1]*p2[1] + Q1[3*i+2]*p2[2];
        float Qr = Q1[3*i+0]*r2[0] + Q1[3*i+1]*r2[1] + Q1[3*i+2]*r2[2];
        np[i] = p1[i] + Qp;
        nr[i] = r1[i] + tau2 * p1[i] + Qr;
    }
    #pragma unroll
    for (int i = 0; i < 9; i++) Q1[i] = nQ[i];
    #pragma unroll
    for (int i = 0; i < 3; i++) { p1[i] = np[i]; r1[i] = nr[i]; }
    tau1 += tau2;
}

// ---------- COLD exact path (never taken on this data) ----------
// Exact scalar re-integration of a 4-step chain from identity.
__device__ void exact_chain4(const float* __restrict__ xb, int kk, int T, int nsteps,
                             float Q[9], float p[3], float r[3], float& tau) {
    Q[0]=1.f;Q[1]=0.f;Q[2]=0.f; Q[3]=0.f;Q[4]=1.f;Q[5]=0.f; Q[6]=0.f;Q[7]=0.f;Q[8]=1.f;
    p[0]=p[1]=p[2]=0.f; r[0]=r[1]=r[2]=0.f; tau=0.f;
    #pragma unroll 1
    for (int j = 0; j < 4; j++) {
        int idx = kk + j;
        float dt = 0.f, wX = 0.f, wY = 0.f, wZ = 0.f, aX = 0.f, aY = 0.f, aZ = 0.f;
        if (idx < nsteps) {
            dt = xb[idx + 1] - xb[idx];
            wX = xb[1*T + idx]; wY = xb[2*T + idx]; wZ = xb[3*T + idx];
            aX = xb[4*T + idx]; aY = xb[5*T + idx]; aZ = xb[6*T + idx];
        }
        float ca0 = Q[0]*aX + Q[1]*aY + Q[2]*aZ;
        float ca1 = Q[3]*aX + Q[4]*aY + Q[5]*aZ;
        float ca2 = Q[6]*aX + Q[7]*aY + Q[8]*aZ;
        float hdt2 = 0.5f * dt * dt;
        r[0] += p[0]*dt + ca0*hdt2;
        r[1] += p[1]*dt + ca1*hdt2;
        r[2] += p[2]*dt + ca2*hdt2;
        p[0] += ca0*dt; p[1] += ca1*dt; p[2] += ca2*dt;
        tau  += dt;

        float px = wX*dt, py = wY*dt, pz = wZ*dt;
        float t2 = px*px + py*py + pz*pz;
        float A, Bc;
        if (t2 < 1e-8f) {
            A  = 1.0f - t2 * (1.0f/6.0f);
            Bc = 0.5f - t2 * (1.0f/24.0f);
        } else {
            float th = sqrtf(t2);
            A  = sinf(th) / th;
            Bc = (1.0f - cosf(th)) / t2;
        }
        float Bxy = Bc*px*py, Bxz = Bc*px*pz, Byz = Bc*py*pz;
        float R00 = 1.0f + Bc*(px*px - t2);
        float R11 = 1.0f + Bc*(py*py - t2);
        float R22 = 1.0f + Bc*(pz*pz - t2);
        float R01 = Bxy - A*pz, R10 = Bxy + A*pz;
        float R02 = Bxz + A*py, R20 = Bxz - A*py;
        float R12 = Byz - A*px, R21 = Byz + A*px;

        float n0 = Q[0]*R00 + Q[1]*R10 + Q[2]*R20;
        float n1 = Q[0]*R01 + Q[1]*R11 + Q[2]*R21;
        float n2 = Q[0]*R02 + Q[1]*R12 + Q[2]*R22;
        float n3 = Q[3]*R00 + Q[4]*R10 + Q[5]*R20;
        float n4 = Q[3]*R01 + Q[4]*R11 + Q[5]*R21;
        float n5 = Q[3]*R02 + Q[4]*R12 + Q[5]*R22;
        float n6 = Q[6]*R00 + Q[7]*R10 + Q[8]*R20;
        float n7 = Q[6]*R01 + Q[7]*R11 + Q[8]*R21;
        float n8 = Q[6]*R02 + Q[7]*R12 + Q[8]*R22;
        Q[0]=n0; Q[1]=n1; Q[2]=n2;
        Q[3]=n3; Q[4]=n4; Q[5]=n5;
        Q[6]=n6; Q[7]=n7; Q[8]=n8;
    }
}

// Tail-guarded float4 channel load (cold/odd-shape path only).
__device__ __forceinline__ float4 loadc(const float* __restrict__ xb, int off, int lim) {
    float t0 = (off + 0 < lim) ? xb[off + 0] : 0.f;
    float t1 = (off + 1 < lim) ? xb[off + 1] : 0.f;
    float t2 = (off + 2 < lim) ? xb[off + 2] : 0.f;
    float t3 = (off + 3 < lim) ? xb[off + 3] : 0.f;
    return make_float4(t0, t1, t2, t3);
}

// One 256-step round for this warp. Result (valid on lane 0) in (Q,p,r,tau).
__device__ __forceinline__ void warp_round(const float* __restrict__ xb,
                                           int k, int T, int nsteps, int lane,
                                           float Q[9], float p[3], float r[3], float& tau) {
    const bool fastld = (k + 7 < T);   // ONE bounds branch for all loads

    // ---- time channel -> packed DT[4]; tv/dts die in this scope ----
    u64 DT[4];
    {
        float tv[8];
        if (fastld) {
            float4 u = *reinterpret_cast<const float4*>(xb + k);
            float4 v = *reinterpret_cast<const float4*>(xb + k + 4);
            tv[0]=u.x; tv[1]=u.y; tv[2]=u.z; tv[3]=u.w;
            tv[4]=v.x; tv[5]=v.y; tv[6]=v.z; tv[7]=v.w;
        } else {
            #pragma unroll
            for (int j = 0; j < 8; j++) tv[j] = (k + j < T) ? xb[k + j] : 0.f;
        }
        float tnext = __shfl_down_sync(0xffffffffu, tv[0], 1);
        if (lane == 31) {
            int kn = k + 8;
            tnext = (kn < T) ? xb[kn] : 0.f;
        }
        float dts[8];
        #pragma unroll
        for (int j = 0; j < 7; j++) dts[j] = tv[j + 1] - tv[j];
        dts[7] = tnext - tv[7];
        #pragma unroll
        for (int j = 0; j < 8; j++)
            if (k + j >= nsteps) dts[j] = 0.f;     // identity step
        DT[0] = pk2(dts[0], dts[4]);
        DT[1] = pk2(dts[1], dts[5]);
        DT[2] = pk2(dts[2], dts[6]);
        DT[3] = pk2(dts[3], dts[7]);
    }

    // ---- load both 4-step chains, pack chainA=.lo / chainB=.hi ----
    float4 wxA, wyA, wzA, axA, ayA, azA;
    float4 wxB, wyB, wzB, axB, ayB, azB;
    if (fastld) {
        wxA = *reinterpret_cast<const float4*>(xb + 1*T + k);
        wxB = *reinterpret_cast<const float4*>(xb + 1*T + k + 4);
        wyA = *reinterpret_cast<const float4*>(xb + 2*T + k);
        wyB = *reinterpret_cast<const float4*>(xb + 2*T + k + 4);
        wzA = *reinterpret_cast<const float4*>(xb + 3*T + k);
        wzB = *reinterpret_cast<const float4*>(xb + 3*T + k + 4);
        axA = *reinterpret_cast<const float4*>(xb + 4*T + k);
        axB = *reinterpret_cast<const float4*>(xb + 4*T + k + 4);
        ayA = *reinterpret_cast<const float4*>(xb + 5*T + k);
        ayB = *reinterpret_cast<const float4*>(xb + 5*T + k + 4);
        azA = *reinterpret_cast<const float4*>(xb + 6*T + k);
        azB = *reinterpret_cast<const float4*>(xb + 6*T + k + 4);
    } else {
        wxA = loadc(xb, 1*T + k, 2*T); wxB = loadc(xb, 1*T + k + 4, 2*T);
        wyA = loadc(xb, 2*T + k, 3*T); wyB = loadc(xb, 2*T + k + 4, 3*T);
        wzA = loadc(xb, 3*T + k, 4*T); wzB = loadc(xb, 3*T + k + 4, 4*T);
        axA = loadc(xb, 4*T + k, 5*T); axB = loadc(xb, 4*T + k + 4, 5*T);
        ayA = loadc(xb, 5*T + k, 6*T); ayB = loadc(xb, 5*T + k + 4, 6*T);
        azA = loadc(xb, 6*T + k, 7*T); azB = loadc(xb, 6*T + k + 4, 7*T);
    }

    // ---- integrate both chains simultaneously (packed, branch-free) ----
    u64 acc = 0ULL;   // sum of packed t2 over 8 steps
    u64 PQ[9], PP[3], PR[3], PT;
    pstep0(PQ, PP, PR, PT, DT[0],
           pk2(axA.x, axB.x), pk2(ayA.x, ayB.x), pk2(azA.x, azB.x),
           pk2(wxA.x, wxB.x), pk2(wyA.x, wyB.x), pk2(wzA.x, wzB.x), acc);
    pstep (PQ, PP, PR, PT, DT[1],
           pk2(axA.y, axB.y), pk2(ayA.y, ayB.y), pk2(azA.y, azB.y),
           pk2(wxA.y, wxB.y), pk2(wyA.y, wyB.y), pk2(wzA.y, wzB.y), acc);
    pstep (PQ, PP, PR, PT, DT[2],
           pk2(axA.z, axB.z), pk2(ayA.z, ayB.z), pk2(azA.z, azB.z),
           pk2(wxA.z, wxB.z), pk2(wyA.z, wyB.z), pk2(wzA.z, wzB.z), acc);
    pstep (PQ, PP, PR, PT, DT[3],
           pk2(axA.w, axB.w), pk2(ayA.w, ayB.w), pk2(azA.w, azB.w),
           pk2(wxA.w, wxB.w), pk2(wyA.w, wyB.w), pk2(wzA.w, wzB.w), acc);

    // ---- unpack ----
    float QB[9], pB[3], rB[3], tauB;
    #pragma unroll
    for (int i = 0; i < 9; i++) up2(PQ[i], Q[i], QB[i]);
    #pragma unroll
    for (int i = 0; i < 3; i++) { up2(PP[i], p[i], pB[i]); up2(PR[i], r[i], rB[i]); }
    up2(PT, tau, tauB);

    // ---- ONE deferred validity check; cold exact re-integration ----
    {
        float mlo, mhi; up2(acc, mlo, mhi);
        if (__builtin_expect(fmaxf(mlo, mhi) > 0.0625f, 0)) {
            exact_chain4(xb, k,     T, nsteps, Q,  p,  r,  tau);
            exact_chain4(xb, k + 4, T, nsteps, QB, pB, rB, tauB);
        }
    }
    compose(Q, p, r, tau, QB, pB, rB, tauB);

    // ---- warp tree reduce (ordered, valid on lane 0) ----
    #pragma unroll
    for (int off = 1; off < 32; off <<= 1) {
        float Q2[9], p2[3], r2[3], tau2;
        #pragma unroll
        for (int i = 0; i < 9; i++) Q2[i] = __shfl_down_sync(0xffffffffu, Q[i], off);
        #pragma unroll
        for (int i = 0; i < 3; i++) p2[i] = __shfl_down_sync(0xffffffffu, p[i], off);
        #pragma unroll
        for (int i = 0; i < 3; i++) r2[i] = __shfl_down_sync(0xffffffffu, r[i], off);
        tau2 = __shfl_down_sync(0xffffffffu, tau, off);
        compose(Q, p, r, tau, Q2, p2, r2, tau2);
    }
}

__global__ __launch_bounds__(128, 5)
void rmi_kernel(const float* __restrict__ x, float* __restrict__ out,
                int T, int chunk)
{
    const int b    = blockIdx.x;
    const int warp = threadIdx.x >> 5;
    const int lane = threadIdx.x & 31;
    const int nsteps = T - 1;

    const float* xb = x + (size_t)b * 7 * (size_t)T;

    const int rounds = chunk >> 8;   // 256 steps per round

    // Round 0 -> warp total directly (total not live during integration)
    float TQ[9], Tp[3], Tr[3], Ttau;
    warp_round(xb, warp * chunk + lane * 8, T, nsteps, lane, TQ, Tp, Tr, Ttau);

    for (int rr = 1; rr < rounds; rr++) {
        float Q[9], p[3], r[3], tau;
        warp_round(xb, warp * chunk + rr * 256 + lane * 8, T, nsteps, lane, Q, p, r, tau);
        compose(TQ, Tp, Tr, Ttau, Q, p, r, tau);
    }

    // ---- cross-warp combine via smem ----
    __shared__ float seg[4][16];
    if (lane == 0) {
        #pragma unroll
        for (int i = 0; i < 9; i++) seg[warp][i] = TQ[i];
        seg[warp][9]  = Tp[0]; seg[warp][10] = Tp[1]; seg[warp][11] = Tp[2];
        seg[warp][12] = Tr[0]; seg[warp][13] = Tr[1]; seg[warp][14] = Tr[2];
        seg[warp][15] = Ttau;
    }
    __syncthreads();

    if (warp == 0 && lane == 0) {
        float FQ[9], Fp[3], Fr[3], Ftau;
        #pragma unroll
        for (int i = 0; i < 9; i++) FQ[i] = seg[0][i];
        Fp[0]=seg[0][9];  Fp[1]=seg[0][10]; Fp[2]=seg[0][11];
        Fr[0]=seg[0][12]; Fr[1]=seg[0][13]; Fr[2]=seg[0][14];
        Ftau = seg[0][15];
        #pragma unroll
        for (int wsg = 1; wsg < 4; wsg++) {
            float Q2[9], p2[3], r2[3], tau2;
            #pragma unroll
            for (int i = 0; i < 9; i++) Q2[i] = seg[wsg][i];
            p2[0]=seg[wsg][9];  p2[1]=seg[wsg][10]; p2[2]=seg[wsg][11];
            r2[0]=seg[wsg][12]; r2[1]=seg[wsg][13]; r2[2]=seg[wsg][14];
            tau2 = seg[wsg][15];
            compose(FQ, Fp, Fr, Ftau, Q2, p2, r2, tau2);
        }
        float* o = out + (size_t)b * 15;
        #pragma unroll
        for (int i = 0; i < 9; i++) o[i] = FQ[i];
        o[9]  = Fp[0]; o[10] = Fp[1]; o[11] = Fp[2];
        o[12] = Fr[0]; o[13] = Fr[1]; o[14] = Fr[2];
    }
}

extern "C" void kernel_launch(void* const* d_in, const int* in_sizes, int n_in,
                              void* d_out, int out_size) {
    const float* x = (const float*)d_in[0];
    float* out = (float*)d_out;

    int B = out_size / 15;
    int T = in_sizes[0] / (7 * B);
    int nsteps = T - 1;

    // per-warp contiguous chunk, multiple of 256, 4 warps cover all steps
    int chunk = ((nsteps + 1023) / 1024) * 256;

    rmi_kernel<<<B, 128>>>(x, out, T, chunk);
}